// round 8
// baseline (speedup 1.0000x reference)
#include <cuda_runtime.h>

// CVCalculator: sliding-window CV, W=60, ddof=1, eps=1e-6.
// flow (16,4096,64) fp32 -> out (16,4096,64), first 59 time rows zero.
//
// Hypothesis under test: gold's cumsum = XLA ReduceWindowRewriter blocked
// scan, base_length=16 (4096 = 16^3, three clean levels):
//   inner0[t]  = sequential inclusive scan within each 16-block of x
//   carry1[b]  = block totals (b=0..255); within 16-groups: inner1 = seq scan,
//   gsum[g]    = group totals (g=0..15);  S2 = seq scan of gsum
//   S1[b]      = fl(S2[g-1] + inner1[b])          (g>0; else inner1)
//   cs[t]      = fl(S1[b-1] + inner0[t])          (b>0; else inner0)
// Epilogue: literal RN ops (provably irrelevant at poles, kept exact anyway):
//   s1 = fl(c1-p1); mean = div.rn(s1,60); denom = fl(mean+1e-6f)
//   var = div.rn(fl(s2 - fl(s1*mean)), 59); cv = div.rn(sqrt.rn(max(var,0)), denom)

#define T_   4096
#define NT   128
#define REG  4416                      // floats per series region
#define SMEM_BYTES (4 * REG * 4)       // 70656 B

// X occupies [0,4128) with skew (idx + idx>>7) -> lane-distinct banks for
// stride-128 sequential sweeps. C1 at 4128 (256), G at 4384 (16).
__device__ __forceinline__ int xa(int i) { return i + (i >> 7); }
#define C1OFF 4128
#define GOFF  4384

__device__ __align__(16) float g_cs1[256 * T_ * 4];   // [block][t][4 feats]

extern "C" __global__ void __launch_bounds__(NT, 1)
cv_kernel(const float* __restrict__ in, float* __restrict__ out)
{
    extern __shared__ float S[];       // 4 series regions of REG floats
    const int tid  = threadIdx.x;
    const int w    = tid >> 5;         // warp = series within quad
    const int ln   = tid & 31;
    const int b    = blockIdx.x >> 4;
    const int q    = blockIdx.x & 15;
    const int fb   = q * 4;

    const float* __restrict__ gin  = in  + (size_t)b * T_ * 64 + fb;
    float* __restrict__       gout = out + (size_t)b * T_ * 64 + fb;
    float* __restrict__       gsc  = g_cs1 + (size_t)blockIdx.x * T_ * 4;

    float* X  = S + w * REG;           // this warp's series
    float* C1 = X + C1OFF;
    float* G  = X + GOFF;

    #pragma unroll 1
    for (int pass = 0; pass < 2; ++pass) {
        // ---- load level-0 (coalesced float4 rows; square on pass 1) ----
        #pragma unroll 1
        for (int t = tid; t < T_; t += NT) {
            float4 v = *reinterpret_cast<const float4*>(gin + (size_t)t * 64);
            if (pass) {
                v.x = __fmul_rn(v.x, v.x); v.y = __fmul_rn(v.y, v.y);
                v.z = __fmul_rn(v.z, v.z); v.w = __fmul_rn(v.w, v.w);
            }
            S[0 * REG + xa(t)] = v.x; S[1 * REG + xa(t)] = v.y;
            S[2 * REG + xa(t)] = v.z; S[3 * REG + xa(t)] = v.w;
        }
        __syncthreads();

        // ---- P1: sequential scan inside each 16-block (8 blocks/lane) ----
        #pragma unroll 1
        for (int k8 = 0; k8 < 8; ++k8) {
            float acc = 0.0f;
            const int base = ln * 128 + k8 * 16;
            #pragma unroll
            for (int i = 0; i < 16; ++i) {
                const int id = base + i;
                acc = __fadd_rn(acc, X[xa(id)]);
                X[xa(id)] = acc;                 // inner0 inclusive, in place
            }
            C1[ln * 8 + k8] = acc;               // block total
        }
        __syncwarp();

        // ---- P2: seq scan of carry1 within 16-groups (lanes 0..15) ----
        if (ln < 16) {
            float acc = 0.0f;
            #pragma unroll
            for (int i = 0; i < 16; ++i) {
                const int bb = ln * 16 + i;
                acc = __fadd_rn(acc, C1[bb]);
                C1[bb] = acc;                    // inner1 inclusive, in place
            }
            G[ln] = acc;                         // group total
        }
        __syncwarp();

        // ---- P3: seq scan of 16 group totals (lane 0) ----
        if (ln == 0) {
            float acc = 0.0f;
            #pragma unroll
            for (int g = 0; g < 16; ++g) {
                acc = __fadd_rn(acc, G[g]);
                G[g] = acc;                      // S2 inclusive
            }
        }
        __syncwarp();

        // ---- P4: S1[b] = fl(S2[g-1] + inner1[b]) ----
        #pragma unroll
        for (int j = 0; j < 8; ++j) {
            const int bb = ln * 8 + j;
            const int g  = bb >> 4;
            if (g > 0) C1[bb] = __fadd_rn(G[g - 1], C1[bb]);
        }
        __syncwarp();

        // ---- P5: cs[t] = fl(S1[b-1] + inner0[t]) ----
        #pragma unroll 1
        for (int j = 0; j < 128; ++j) {
            const int id = ln * 128 + j;
            const int bb = id >> 4;
            if (bb > 0) X[xa(id)] = __fadd_rn(C1[bb - 1], X[xa(id)]);
        }
        __syncthreads();

        // ---- stash cs1 (pass 0) to global scratch ----
        if (pass == 0) {
            #pragma unroll 1
            for (int t = tid; t < T_; t += NT) {
                float4 u;
                u.x = S[0 * REG + xa(t)]; u.y = S[1 * REG + xa(t)];
                u.z = S[2 * REG + xa(t)]; u.w = S[3 * REG + xa(t)];
                *reinterpret_cast<float4*>(gsc + (size_t)t * 4) = u;
            }
            __syncthreads();
        }
    }

    // ---- epilogue: literal RN ops ----
    #pragma unroll 1
    for (int t = tid; t < T_; t += NT) {
        float o[4];
        if (t < 59) {
            o[0] = o[1] = o[2] = o[3] = 0.0f;
        } else {
            float4 c1 = *reinterpret_cast<const float4*>(gsc + (size_t)t * 4);
            float4 p1 = make_float4(0.f, 0.f, 0.f, 0.f);
            float  p2[4] = {0.f, 0.f, 0.f, 0.f};
            if (t >= 60) {
                p1 = *reinterpret_cast<const float4*>(gsc + (size_t)(t - 60) * 4);
                #pragma unroll
                for (int s = 0; s < 4; ++s) p2[s] = S[s * REG + xa(t - 60)];
            }
            float c1a[4] = {c1.x, c1.y, c1.z, c1.w};
            float p1a[4] = {p1.x, p1.y, p1.z, p1.w};
            #pragma unroll
            for (int s = 0; s < 4; ++s) {
                float s1 = __fsub_rn(c1a[s], p1a[s]);
                float s2 = __fsub_rn(S[s * REG + xa(t)], p2[s]);
                float mean  = __fdiv_rn(s1, 60.0f);
                float denom = __fadd_rn(mean, 1e-6f);
                float var   = __fdiv_rn(__fsub_rn(s2, __fmul_rn(s1, mean)), 59.0f);
                var = fmaxf(var, 0.0f);
                o[s] = __fdiv_rn(__fsqrt_rn(var), denom);
            }
        }
        float4 ov = make_float4(o[0], o[1], o[2], o[3]);
        *reinterpret_cast<float4*>(gout + (size_t)t * 64) = ov;
    }
}

extern "C" void kernel_launch(void* const* d_in, const int* in_sizes, int n_in,
                              void* d_out, int out_size) {
    (void)in_sizes; (void)n_in; (void)out_size;
    cudaFuncSetAttribute(cv_kernel, cudaFuncAttributeMaxDynamicSharedMemorySize,
                         SMEM_BYTES);
    cv_kernel<<<256, NT, SMEM_BYTES>>>((const float*)d_in[0], (float*)d_out);
}

// round 10
// speedup vs baseline: 1.7917x; 1.7917x over previous
#include <cuda_runtime.h>

// CVCalculator: sliding-window CV, W=60, ddof=1, eps=1e-6.
// flow (16,4096,64) fp32 -> out (16,4096,64), first 59 time rows zero.
//
// Gold-matching cumsum = XLA ReduceWindowRewriter blocked scan, base 16:
//   inner0 = seq scan within 16-blocks; carries scanned within 16-groups;
//   group totals scanned; S1[b] = S2[g-1]+inner1[b]; cs[t] = S1[b-1]+inner0[t].
// Pole-critical epilogue ops (exact, order-preserved):
//   mean = div.rn(s1, 60); denom = fl(mean + 1e-6f)
// Numerator ops are relative-accuracy tolerant -> FMA/approx (error ~1e-7).
//
// Single pass: CTA = 4 features x {x, x^2} = 8 series, one warp per series,
// both cumsums smem-resident. 16-block stride 20 floats (ADDITIVE offset!)
// -> all P1/P5 LDS.128/STS.128 are aligned and bank-conflict-free.

#define T_      4096
#define NT      256
#define REGION  5120                    // 256 blocks * 20 floats
#define CBASE   (8 * REGION)            // 40960
#define CSTRIDE 272                     // 256 carries + 16 group sums
#define SMEM_BYTES ((CBASE + 8 * CSTRIDE) * 4)   // 172544 B

// additive: block stride 20 has nonzero low bits, OR would corrupt (R9 bug)
__device__ __forceinline__ int taddr(int t) { return (t >> 4) * 20 + (t & 15); }

extern "C" __global__ void __launch_bounds__(NT, 1)
cv_kernel(const float* __restrict__ in, float* __restrict__ out)
{
    extern __shared__ float S[];
    const int tid = threadIdx.x;
    const int w   = tid >> 5;           // warp 0..7 = series (feat, kind)
    const int ln  = tid & 31;
    const int bat = blockIdx.x >> 4;
    const int fb  = (blockIdx.x & 15) * 4;

    const float* __restrict__ gin  = in  + (size_t)bat * T_ * 64 + fb;
    float* __restrict__       gout = out + (size_t)bat * T_ * 64 + fb;

    // ---- load: x -> series 0..3, x^2 -> series 4..7 ----
    #pragma unroll
    for (int k = 0; k < 16; ++k) {
        const int t  = tid + (k << 8);
        float4 v = *reinterpret_cast<const float4*>(gin + (size_t)t * 64);
        const int at = taddr(t);
        S[0 * REGION + at] = v.x;
        S[1 * REGION + at] = v.y;
        S[2 * REGION + at] = v.z;
        S[3 * REGION + at] = v.w;
        S[4 * REGION + at] = __fmul_rn(v.x, v.x);
        S[5 * REGION + at] = __fmul_rn(v.y, v.y);
        S[6 * REGION + at] = __fmul_rn(v.z, v.z);
        S[7 * REGION + at] = __fmul_rn(v.w, v.w);
    }
    __syncthreads();

    float* __restrict__ X = S + w * REGION;
    float* __restrict__ C = S + CBASE + w * CSTRIDE;
    float* __restrict__ G = C + 256;

    // ---- P1: seq scan inside each 16-block, in registers ----
    #pragma unroll 2
    for (int j = 0; j < 8; ++j) {
        const int blk = ln + 32 * j;
        float* p = X + blk * 20;
        float4 a = *reinterpret_cast<float4*>(p);
        float4 q = *reinterpret_cast<float4*>(p + 4);
        float4 r = *reinterpret_cast<float4*>(p + 8);
        float4 d = *reinterpret_cast<float4*>(p + 12);
        a.y = __fadd_rn(a.x, a.y); a.z = __fadd_rn(a.y, a.z); a.w = __fadd_rn(a.z, a.w);
        q.x = __fadd_rn(a.w, q.x); q.y = __fadd_rn(q.x, q.y);
        q.z = __fadd_rn(q.y, q.z); q.w = __fadd_rn(q.z, q.w);
        r.x = __fadd_rn(q.w, r.x); r.y = __fadd_rn(r.x, r.y);
        r.z = __fadd_rn(r.y, r.z); r.w = __fadd_rn(r.z, r.w);
        d.x = __fadd_rn(r.w, d.x); d.y = __fadd_rn(d.x, d.y);
        d.z = __fadd_rn(d.y, d.z); d.w = __fadd_rn(d.z, d.w);
        *reinterpret_cast<float4*>(p)      = a;
        *reinterpret_cast<float4*>(p + 4)  = q;
        *reinterpret_cast<float4*>(p + 8)  = r;
        *reinterpret_cast<float4*>(p + 12) = d;
        C[blk] = d.w;                      // block total
    }
    __syncwarp();

    // ---- P2: seq scan of carries within 16-groups (lanes 0..15) ----
    if (ln < 16) {
        float acc = 0.0f;
        #pragma unroll
        for (int i = 0; i < 16; ++i) {
            const int bb = ln * 16 + i;
            acc = __fadd_rn(acc, C[bb]);
            C[bb] = acc;                   // inner1 inclusive
        }
        G[ln] = acc;
    }
    __syncwarp();

    // ---- P3: seq scan of 16 group totals (lane 0) ----
    if (ln == 0) {
        float acc = 0.0f;
        #pragma unroll
        for (int g = 0; g < 16; ++g) {
            acc = __fadd_rn(acc, G[g]);
            G[g] = acc;                    // S2 inclusive
        }
    }
    __syncwarp();

    // ---- P4: S1[b] = fl(S2[g-1] + inner1[b]) ----
    #pragma unroll
    for (int j = 0; j < 8; ++j) {
        const int bb = ln + 32 * j;
        const int g  = bb >> 4;
        if (g > 0) C[bb] = __fadd_rn(G[g - 1], C[bb]);
    }
    __syncwarp();

    // ---- P5: cs[t] = fl(S1[b-1] + inner0[t]), vectorized ----
    #pragma unroll 2
    for (int j = 0; j < 8; ++j) {
        const int blk = ln + 32 * j;
        if (blk > 0) {
            const float cc = C[blk - 1];
            float* p = X + blk * 20;
            #pragma unroll
            for (int h = 0; h < 4; ++h) {
                float4 v = *reinterpret_cast<float4*>(p + 4 * h);
                v.x = __fadd_rn(cc, v.x); v.y = __fadd_rn(cc, v.y);
                v.z = __fadd_rn(cc, v.z); v.w = __fadd_rn(cc, v.w);
                *reinterpret_cast<float4*>(p + 4 * h) = v;
            }
        }
    }
    __syncthreads();

    // ---- epilogue ----
    #pragma unroll 1
    for (int k = 0; k < 16; ++k) {
        const int t = tid + (k << 8);
        float o[4];
        if (t < 59) {
            o[0] = o[1] = o[2] = o[3] = 0.0f;
        } else {
            const int at = taddr(t);
            const int ap = (t >= 60) ? taddr(t - 60) : 0;
            #pragma unroll
            for (int f = 0; f < 4; ++f) {
                float c1 = S[f * REGION + at];
                float c2 = S[(f + 4) * REGION + at];
                float p1 = 0.0f, p2 = 0.0f;
                if (t >= 60) {
                    p1 = S[f * REGION + ap];
                    p2 = S[(f + 4) * REGION + ap];
                }
                float s1 = __fsub_rn(c1, p1);
                float s2 = __fsub_rn(c2, p2);
                float mean  = __fdiv_rn(s1, 60.0f);      // pole-critical
                float denom = __fadd_rn(mean, 1e-6f);    // pole-critical
                float var = __fmul_rn(__fmaf_rn(-s1, mean, s2), 1.0f / 59.0f);
                float std = (var > 0.0f)
                          ? __fmul_rn(var, __frsqrt_rn(var)) : 0.0f;
                o[f] = __fdividef(std, denom);
            }
        }
        float4 ov = make_float4(o[0], o[1], o[2], o[3]);
        *reinterpret_cast<float4*>(gout + (size_t)t * 64) = ov;
    }
}

extern "C" void kernel_launch(void* const* d_in, const int* in_sizes, int n_in,
                              void* d_out, int out_size) {
    (void)in_sizes; (void)n_in; (void)out_size;
    cudaFuncSetAttribute(cv_kernel, cudaFuncAttributeMaxDynamicSharedMemorySize,
                         SMEM_BYTES);
    cv_kernel<<<256, NT, SMEM_BYTES>>>((const float*)d_in[0], (float*)d_out);
}

// round 11
// speedup vs baseline: 2.6909x; 1.5019x over previous
#include <cuda_runtime.h>

// CVCalculator: sliding-window CV, W=60, ddof=1, eps=1e-6.
// flow (16,4096,64) fp32 -> out (16,4096,64), first 59 time rows zero.
//
// Gold-matching cumsum = XLA ReduceWindowRewriter blocked scan, base 16
// (verified R8/R10): inner0 = seq scan within 16-blocks; carries scanned
// within 16-groups; group totals scanned; S1[b]=fl(S2[g-1]+inner1[b]);
// cs[t]=fl(S1[b-1]+inner0[t]). Pole-critical epilogue ops kept exact:
// mean = div.rn(s1,60); denom = fl(mean+1e-6f). Numerator relaxed (rel ~1e-7).
//
// Layout: [kind][block][ti][feat4] -> every smem access is LDS/STS.128,
// block stride 68 floats => conflict-free. Inner scans live in registers;
// cs written once (staging reused). 512 thr/CTA, 1 unit per thread.

#define T_     4096
#define NT     512
#define KSTR   17408                  // 256 blocks * 68 floats per kind
#define CB     (2 * KSTR)             // carries base  (34816)
#define CKSTR  1104                   // 16 groups * 68 + 16
#define GB     (CB + 2 * CKSTR)       // group-total base (37024)
#define GKSTR  68
#define SMEM_BYTES ((GB + 2 * GKSTR) * 4)   // 148640 B

__device__ __forceinline__ int taddr(int kind, int t) {
    return kind * KSTR + (t >> 4) * 68 + (t & 15) * 4;
}
__device__ __forceinline__ float4 f4add(float c, float4 v) {
    float4 r;
    r.x = __fadd_rn(c, v.x); r.y = __fadd_rn(c, v.y);
    r.z = __fadd_rn(c, v.z); r.w = __fadd_rn(c, v.w);
    return r;
}
__device__ __forceinline__ float4 f4addv(float4 a, float4 v) {
    float4 r;
    r.x = __fadd_rn(a.x, v.x); r.y = __fadd_rn(a.y, v.y);
    r.z = __fadd_rn(a.z, v.z); r.w = __fadd_rn(a.w, v.w);
    return r;
}

extern "C" __global__ void __launch_bounds__(NT, 1)
cv_kernel(const float* __restrict__ in, float* __restrict__ out)
{
    extern __shared__ float S[];
    const int tid = threadIdx.x;
    const int bat = blockIdx.x >> 4;
    const int fb  = (blockIdx.x & 15) * 4;

    const float* __restrict__ gin  = in  + (size_t)bat * T_ * 64 + fb;
    float* __restrict__       gout = out + (size_t)bat * T_ * 64 + fb;

    // ---- stage: x -> kind0, x^2 -> kind1 (all STS.128) ----
    #pragma unroll
    for (int k = 0; k < 8; ++k) {
        const int t = tid + (k << 9);
        float4 v = *reinterpret_cast<const float4*>(gin + (size_t)t * 64);
        float4 s;
        s.x = __fmul_rn(v.x, v.x); s.y = __fmul_rn(v.y, v.y);
        s.z = __fmul_rn(v.z, v.z); s.w = __fmul_rn(v.w, v.w);
        *reinterpret_cast<float4*>(S + taddr(0, t)) = v;
        *reinterpret_cast<float4*>(S + taddr(1, t)) = s;
    }
    __syncthreads();

    // ---- P1: seq scan of one 16-block per thread, in registers ----
    const int kind = tid >> 8;
    const int blk  = tid & 255;
    float* __restrict__ base = S + kind * KSTR + blk * 68;
    float4 r[16];
    #pragma unroll
    for (int i = 0; i < 16; ++i)
        r[i] = *reinterpret_cast<const float4*>(base + 4 * i);
    #pragma unroll
    for (int i = 1; i < 16; ++i)
        r[i] = f4addv(r[i - 1], r[i]);
    // block total -> carries
    *reinterpret_cast<float4*>(S + CB + kind * CKSTR + (blk >> 4) * 68
                               + (blk & 15) * 4) = r[15];
    __syncthreads();

    // ---- P2: scan carries within 16-groups (warp 0, one lane per unit) ----
    if (tid < 32) {
        const int kk = tid >> 4, g = tid & 15;
        float* __restrict__ c = S + CB + kk * CKSTR + g * 68;
        float4 acc = make_float4(0.f, 0.f, 0.f, 0.f);
        #pragma unroll
        for (int i = 0; i < 16; ++i) {
            float4 v = *reinterpret_cast<const float4*>(c + 4 * i);
            acc = f4addv(acc, v);
            *reinterpret_cast<float4*>(c + 4 * i) = acc;   // inner1 inclusive
        }
        *reinterpret_cast<float4*>(S + GB + kk * GKSTR + g * 4) = acc;
    }
    __syncwarp();
    // ---- P3: scan 16 group totals per kind (lanes 0,1) ----
    if (tid < 2) {
        float* __restrict__ gbuf = S + GB + tid * GKSTR;
        float4 acc = make_float4(0.f, 0.f, 0.f, 0.f);
        #pragma unroll
        for (int g = 0; g < 16; ++g) {
            float4 v = *reinterpret_cast<const float4*>(gbuf + 4 * g);
            acc = f4addv(acc, v);
            *reinterpret_cast<float4*>(gbuf + 4 * g) = acc; // S2 inclusive
        }
    }
    __syncthreads();

    // ---- P5 (P4 folded): cs = fl(S1[blk-1] + inner0), write once ----
    if (blk > 0) {
        const int pb = blk - 1, pg = pb >> 4;
        float4 carry = *reinterpret_cast<const float4*>(
            S + CB + kind * CKSTR + pg * 68 + (pb & 15) * 4);   // inner1[pb]
        if (pg > 0) {
            float4 s2 = *reinterpret_cast<const float4*>(
                S + GB + kind * GKSTR + (pg - 1) * 4);
            // S1[pb] = fl(S2[pg-1] + inner1[pb])  (same order as R10 P4)
            carry.x = __fadd_rn(s2.x, carry.x);
            carry.y = __fadd_rn(s2.y, carry.y);
            carry.z = __fadd_rn(s2.z, carry.z);
            carry.w = __fadd_rn(s2.w, carry.w);
        }
        #pragma unroll
        for (int i = 0; i < 16; ++i) {
            float4 v;
            v.x = __fadd_rn(carry.x, r[i].x);
            v.y = __fadd_rn(carry.y, r[i].y);
            v.z = __fadd_rn(carry.z, r[i].z);
            v.w = __fadd_rn(carry.w, r[i].w);
            *reinterpret_cast<float4*>(base + 4 * i) = v;
        }
    } else {
        #pragma unroll
        for (int i = 0; i < 16; ++i)
            *reinterpret_cast<float4*>(base + 4 * i) = r[i];
    }
    __syncthreads();

    // ---- epilogue: 4x LDS.128 + math + STG.128 per t ----
    #pragma unroll 2
    for (int k = 0; k < 8; ++k) {
        const int t = tid + (k << 9);
        float4 o;
        if (t < 59) {
            o = make_float4(0.f, 0.f, 0.f, 0.f);
        } else {
            float4 c1 = *reinterpret_cast<const float4*>(S + taddr(0, t));
            float4 c2 = *reinterpret_cast<const float4*>(S + taddr(1, t));
            float4 p1 = make_float4(0.f, 0.f, 0.f, 0.f);
            float4 p2 = make_float4(0.f, 0.f, 0.f, 0.f);
            if (t >= 60) {
                p1 = *reinterpret_cast<const float4*>(S + taddr(0, t - 60));
                p2 = *reinterpret_cast<const float4*>(S + taddr(1, t - 60));
            }
            const float* c1a = &c1.x; const float* c2a = &c2.x;
            const float* p1a = &p1.x; const float* p2a = &p2.x;
            float* oa = &o.x;
            #pragma unroll
            for (int f = 0; f < 4; ++f) {
                float s1 = __fsub_rn(c1a[f], p1a[f]);
                float s2 = __fsub_rn(c2a[f], p2a[f]);
                float mean  = __fdiv_rn(s1, 60.0f);      // pole-critical
                float denom = __fadd_rn(mean, 1e-6f);    // pole-critical
                float var = __fmul_rn(__fmaf_rn(-s1, mean, s2), 1.0f / 59.0f);
                float std = (var > 0.0f)
                          ? __fmul_rn(var, __frsqrt_rn(var)) : 0.0f;
                oa[f] = __fdividef(std, denom);
            }
        }
        *reinterpret_cast<float4*>(gout + (size_t)t * 64) = o;
    }
}

extern "C" void kernel_launch(void* const* d_in, const int* in_sizes, int n_in,
                              void* d_out, int out_size) {
    (void)in_sizes; (void)n_in; (void)out_size;
    cudaFuncSetAttribute(cv_kernel, cudaFuncAttributeMaxDynamicSharedMemorySize,
                         SMEM_BYTES);
    cv_kernel<<<256, NT, SMEM_BYTES>>>((const float*)d_in[0], (float*)d_out);
}